// round 4
// baseline (speedup 1.0000x reference)
#include <cuda_runtime.h>
#include <cuda_bf16.h>
#include <math_constants.h>

// Problem constants (fixed shapes)
#define B_   8
#define C_   21
#define H_   512
#define W_   512
#define HW_  (H_ * W_)           // 262144 = 2^18
#define HW_SHIFT 18
#define NPIX (B_ * HW_)          // 2097152
#define MAX_M 0.5f
#define S_    30.0f

#define HIST_BLOCKS 512
#define LOSS_BLOCKS (NPIX / 4 / 256)   // 2048

// Scratch (device globals, all overwrite-deterministic — no init kernel needed)
__device__ int   g_parts[HIST_BLOCKS][C_];   // per-block histogram partials
__device__ float g_mlist[C_];
__device__ float g_lparts[LOSS_BLOCKS];      // per-block nll sums

// ---------------------------------------------------------------------------
// Kernel 1: per-block label histograms (per-warp smem sub-histograms)
// ---------------------------------------------------------------------------
__global__ __launch_bounds__(256) void hist_kernel(const int* __restrict__ target) {
    __shared__ int sh[8][C_];
    int wid  = threadIdx.x >> 5;
    for (int i = threadIdx.x; i < 8 * C_; i += 256)
        (&sh[0][0])[i] = 0;
    __syncthreads();

    const int4* t4 = reinterpret_cast<const int4*>(target);
    int n4 = NPIX / 4;
    for (int i = blockIdx.x * blockDim.x + threadIdx.x; i < n4;
         i += gridDim.x * blockDim.x) {
        int4 v = t4[i];
        atomicAdd(&sh[wid][v.x], 1);
        atomicAdd(&sh[wid][v.y], 1);
        atomicAdd(&sh[wid][v.z], 1);
        atomicAdd(&sh[wid][v.w], 1);
    }
    __syncthreads();
    if (threadIdx.x < C_) {
        int s = 0;
#pragma unroll
        for (int w = 0; w < 8; w++) s += sh[w][threadIdx.x];
        g_parts[blockIdx.x][threadIdx.x] = s;   // plain store (deterministic)
    }
}

// ---------------------------------------------------------------------------
// Kernel 2: reduce partials -> counts -> m_list  (21 warps; warp w owns class w)
// ---------------------------------------------------------------------------
__global__ void mlist_kernel() {
    __shared__ float cnt[C_];
    int w    = threadIdx.x >> 5;   // 0..20
    int lane = threadIdx.x & 31;

    int s = 0;
    for (int p = lane; p < HIST_BLOCKS; p += 32) s += g_parts[p][w];
#pragma unroll
    for (int o = 16; o > 0; o >>= 1) s += __shfl_xor_sync(0xffffffffu, s, o);
    if (lane == 0) cnt[w] = (float)s;
    __syncthreads();

    if (w == 0) {
        float mi = 0.0f, m = -CUDART_INF_F;
        if (lane < C_) {
            mi = rsqrtf(sqrtf(cnt[lane] + 1e-4f));
            m  = mi;
        }
#pragma unroll
        for (int o = 16; o > 0; o >>= 1)
            m = fmaxf(m, __shfl_xor_sync(0xffffffffu, m, o));
        if (lane < C_) g_mlist[lane] = mi * (MAX_M / m);
    }
}

// ---------------------------------------------------------------------------
// Kernel 3: LDAM NLL, 4 pixels/thread, margin handled as epilogue correction.
//
// Stabilizer uses the RAW channel max M (>= margined max): all exp args <= 0
// and the surviving target term >= exp(-S*MAX_M) = exp(-15), so no under/over-
// flow. Target correction: s = max(s_raw - e_l, 0) + e_{l,m}; the fmax guard
// keeps s strictly positive against float cancellation.
// ---------------------------------------------------------------------------
__device__ __forceinline__ float pixel_nll(const float* __restrict__ base,
                                           int hw_p, int l, float maxv, float s_raw) {
    float m   = g_mlist[l];
    float xl  = __ldg(base + (size_t)l * HW_ + hw_p);     // L1 hit (line just loaded)
    float el  = __expf(S_ * (xl - maxv));
    float elm = __expf(S_ * (xl - m - maxv));
    float s   = fmaxf(s_raw - el, 0.0f) + elm;
    return __logf(s) + S_ * (maxv - (xl - m));
}

__global__ __launch_bounds__(256) void loss_kernel(const float* __restrict__ pred,
                                                   const int*   __restrict__ target) {
    int t    = blockIdx.x * 256 + threadIdx.x;
    int pix0 = t * 4;                       // 4 consecutive pixels, same batch b
    int b    = pix0 >> HW_SHIFT;
    int hw   = pix0 & (HW_ - 1);
    const float* base = pred + (size_t)(b * C_) * HW_ + hw;

    float4 v[C_];
    float4 mx = make_float4(-CUDART_INF_F, -CUDART_INF_F, -CUDART_INF_F, -CUDART_INF_F);
#pragma unroll
    for (int c = 0; c < C_; c++) {
        float4 x = __ldg(reinterpret_cast<const float4*>(base + (size_t)c * HW_));
        v[c] = x;
        mx.x = fmaxf(mx.x, x.x);
        mx.y = fmaxf(mx.y, x.y);
        mx.z = fmaxf(mx.z, x.z);
        mx.w = fmaxf(mx.w, x.w);
    }

    float4 s = make_float4(0.f, 0.f, 0.f, 0.f);
#pragma unroll
    for (int c = 0; c < C_; c++) {
        s.x += __expf(S_ * (v[c].x - mx.x));
        s.y += __expf(S_ * (v[c].y - mx.y));
        s.z += __expf(S_ * (v[c].z - mx.z));
        s.w += __expf(S_ * (v[c].w - mx.w));
    }

    int4 lab = __ldg(reinterpret_cast<const int4*>(target + pix0));

    float nll = pixel_nll(base, hw + 0 - hw + 0, lab.x, mx.x, s.x);
    // note: pixel offsets within the thread's 4-pixel group
    nll += pixel_nll(base + 1, 0, lab.y, mx.y, s.y);
    nll += pixel_nll(base + 2, 0, lab.z, mx.z, s.z);
    nll += pixel_nll(base + 3, 0, lab.w, mx.w, s.w);

    // Warp reduce, then cross-warp, one plain store per block (deterministic)
#pragma unroll
    for (int o = 16; o > 0; o >>= 1)
        nll += __shfl_xor_sync(0xffffffffu, nll, o);

    __shared__ float warp_sums[8];
    int lane = threadIdx.x & 31;
    int wid  = threadIdx.x >> 5;
    if (lane == 0) warp_sums[wid] = nll;
    __syncthreads();

    if (wid == 0) {
        float x = (lane < 8) ? warp_sums[lane] : 0.0f;
#pragma unroll
        for (int o = 4; o > 0; o >>= 1)
            x += __shfl_xor_sync(0xffffffffu, x, o);
        if (lane == 0) g_lparts[blockIdx.x] = x;
    }
}

// ---------------------------------------------------------------------------
// Kernel 4: finalize — f64 reduction of block partials, mean, f32 out
// ---------------------------------------------------------------------------
__global__ void finalize_kernel(float* __restrict__ out) {
    __shared__ double sm[256];
    double s = 0.0;
    for (int i = threadIdx.x; i < LOSS_BLOCKS; i += 256)
        s += (double)g_lparts[i];
    sm[threadIdx.x] = s;
    __syncthreads();
#pragma unroll
    for (int o = 128; o > 0; o >>= 1) {
        if (threadIdx.x < o) sm[threadIdx.x] += sm[threadIdx.x + o];
        __syncthreads();
    }
    if (threadIdx.x == 0) out[0] = (float)(sm[0] * (1.0 / (double)NPIX));
}

// ---------------------------------------------------------------------------
extern "C" void kernel_launch(void* const* d_in, const int* in_sizes, int n_in,
                              void* d_out, int out_size) {
    const float* pred   = (const float*)d_in[0];
    const int*   target = (const int*)d_in[1];
    float*       out    = (float*)d_out;

    hist_kernel<<<HIST_BLOCKS, 256>>>(target);
    mlist_kernel<<<1, C_ * 32>>>();
    loss_kernel<<<LOSS_BLOCKS, 256>>>(pred, target);
    finalize_kernel<<<1, 256>>>(out);
}

// round 5
// speedup vs baseline: 1.1285x; 1.1285x over previous
#include <cuda_runtime.h>
#include <cuda_bf16.h>
#include <math_constants.h>

// Problem constants (fixed shapes)
#define B_   8
#define C_   21
#define H_   512
#define W_   512
#define HW_  (H_ * W_)           // 262144 = 2^18
#define HW_SHIFT 18
#define NPIX (B_ * HW_)          // 2097152
#define MAX_M 0.5f
#define S_    30.0f

#define HIST_BLOCKS 512

// Scratch (device globals — no allocations allowed)
__device__ int    g_parts[HIST_BLOCKS][C_];  // per-block histogram partials
__device__ float  g_mlist[C_];
__device__ double g_loss;

// ---------------------------------------------------------------------------
// Kernel 1: per-block label histograms (per-warp smem sub-histograms).
// Block 0 / thread 0 also zeroes g_loss (only consumed by strictly-later
// kernels in the graph, so this is deterministic and race-free).
// ---------------------------------------------------------------------------
__global__ __launch_bounds__(256) void hist_kernel(const int* __restrict__ target) {
    __shared__ int sh[8][C_];
    int wid = threadIdx.x >> 5;
    for (int i = threadIdx.x; i < 8 * C_; i += 256)
        (&sh[0][0])[i] = 0;
    if (blockIdx.x == 0 && threadIdx.x == 0) g_loss = 0.0;
    __syncthreads();

    const int4* t4 = reinterpret_cast<const int4*>(target);
    int n4 = NPIX / 4;
    for (int i = blockIdx.x * blockDim.x + threadIdx.x; i < n4;
         i += gridDim.x * blockDim.x) {
        int4 v = t4[i];
        atomicAdd(&sh[wid][v.x], 1);
        atomicAdd(&sh[wid][v.y], 1);
        atomicAdd(&sh[wid][v.z], 1);
        atomicAdd(&sh[wid][v.w], 1);
    }
    __syncthreads();
    if (threadIdx.x < C_) {
        int s = 0;
#pragma unroll
        for (int w = 0; w < 8; w++) s += sh[w][threadIdx.x];
        g_parts[blockIdx.x][threadIdx.x] = s;
    }
}

// ---------------------------------------------------------------------------
// Kernel 2: reduce partials -> counts -> m_list  (21 warps; warp w owns class w)
// ---------------------------------------------------------------------------
__global__ void mlist_kernel() {
    __shared__ float cnt[C_];
    int w    = threadIdx.x >> 5;   // 0..20
    int lane = threadIdx.x & 31;

    int s = 0;
    for (int p = lane; p < HIST_BLOCKS; p += 32) s += g_parts[p][w];
#pragma unroll
    for (int o = 16; o > 0; o >>= 1) s += __shfl_xor_sync(0xffffffffu, s, o);
    if (lane == 0) cnt[w] = (float)s;
    __syncthreads();

    if (w == 0) {
        float mi = 0.0f, m = -CUDART_INF_F;
        if (lane < C_) {
            mi = rsqrtf(sqrtf(cnt[lane] + 1e-4f));
            m  = mi;
        }
#pragma unroll
        for (int o = 16; o > 0; o >>= 1)
            m = fmaxf(m, __shfl_xor_sync(0xffffffffu, m, o));
        if (lane < C_) g_mlist[lane] = mi * (MAX_M / m);
    }
}

// ---------------------------------------------------------------------------
// Kernel 3: LDAM NLL, 2 pixels/thread (float2), margin as epilogue correction.
//
// Stabilizer uses the RAW channel max (>= margined max): all exp args <= 0
// and the surviving target term >= exp(-S*MAX_M) = exp(-15) -> no under/over-
// flow. Per-pixel patch: s = max(s_raw - e_l, 0) + e_{l-m}; the fmax guard
// keeps s strictly positive against float cancellation. x_l is re-read from
// global; the line was just loaded by this warp, so it is an L1 hit.
// ---------------------------------------------------------------------------
__device__ __forceinline__ float pixel_nll(const float* __restrict__ p_lx,
                                           int l, float maxv, float s_raw) {
    float m   = g_mlist[l];
    float xl  = __ldg(p_lx);
    float el  = __expf(S_ * (xl - maxv));
    float elm = __expf(S_ * (xl - m - maxv));
    float s   = fmaxf(s_raw - el, 0.0f) + elm;
    return __logf(s) + S_ * (maxv - (xl - m));
}

__global__ __launch_bounds__(256) void loss_kernel(const float* __restrict__ pred,
                                                   const int*   __restrict__ target) {
    int t    = blockIdx.x * 256 + threadIdx.x;
    int pix0 = t * 2;                       // 2 consecutive pixels, same batch
    int b    = pix0 >> HW_SHIFT;
    int hw   = pix0 & (HW_ - 1);
    const float* base = pred + (size_t)(b * C_) * HW_ + hw;

    float2 v[C_];
    float mx0 = -CUDART_INF_F, mx1 = -CUDART_INF_F;
#pragma unroll
    for (int c = 0; c < C_; c++) {
        float2 x = __ldg(reinterpret_cast<const float2*>(base + (size_t)c * HW_));
        v[c] = x;
        mx0 = fmaxf(mx0, x.x);
        mx1 = fmaxf(mx1, x.y);
    }

    float s0 = 0.0f, s1 = 0.0f;
#pragma unroll
    for (int c = 0; c < C_; c++) {
        s0 += __expf(S_ * (v[c].x - mx0));
        s1 += __expf(S_ * (v[c].y - mx1));
    }

    int2 lab = __ldg(reinterpret_cast<const int2*>(target + pix0));

    float nll = pixel_nll(base + (size_t)lab.x * HW_,     lab.x, mx0, s0)
              + pixel_nll(base + (size_t)lab.y * HW_ + 1, lab.y, mx1, s1);

    // Warp reduce, cross-warp via smem, one f64 atomic per block.
#pragma unroll
    for (int o = 16; o > 0; o >>= 1)
        nll += __shfl_xor_sync(0xffffffffu, nll, o);

    __shared__ float warp_sums[8];
    int lane = threadIdx.x & 31;
    int wid  = threadIdx.x >> 5;
    if (lane == 0) warp_sums[wid] = nll;
    __syncthreads();

    if (wid == 0) {
        float x = (lane < 8) ? warp_sums[lane] : 0.0f;
#pragma unroll
        for (int o = 4; o > 0; o >>= 1)
            x += __shfl_xor_sync(0xffffffffu, x, o);
        if (lane == 0) atomicAdd(&g_loss, (double)x);
    }
}

// ---------------------------------------------------------------------------
// Kernel 4: finalize — mean, write f32 scalar
// ---------------------------------------------------------------------------
__global__ void finalize_kernel(float* __restrict__ out) {
    out[0] = (float)(g_loss * (1.0 / (double)NPIX));
}

// ---------------------------------------------------------------------------
extern "C" void kernel_launch(void* const* d_in, const int* in_sizes, int n_in,
                              void* d_out, int out_size) {
    const float* pred   = (const float*)d_in[0];
    const int*   target = (const int*)d_in[1];
    float*       out    = (float*)d_out;

    hist_kernel<<<HIST_BLOCKS, 256>>>(target);
    mlist_kernel<<<1, C_ * 32>>>();
    loss_kernel<<<NPIX / 2 / 256, 256>>>(pred, target);
    finalize_kernel<<<1, 1>>>(out);
}